// round 2
// baseline (speedup 1.0000x reference)
#include <cuda_runtime.h>
#include <cuda_bf16.h>

// Problem constants
#define BB   4
#define SS   2048
#define DM   1024
#define HH   16
#define DH   64
#define ROWS (BB*SS)          // 8192
#define OUTE  8388608LL       // B*S*DM
#define ATTNE 268435456LL     // B*H*S*S

typedef unsigned long long ull;

// ---------------- f32x2 helpers (full-rate FP32 on sm_103a) ----------------
__device__ __forceinline__ ull pk(float x, float y) {
    ull r; asm("mov.b64 %0, {%1, %2};" : "=l"(r) : "f"(x), "f"(y)); return r;
}
__device__ __forceinline__ ull fma2_(ull a, ull b, ull c) {
    ull d; asm("fma.rn.f32x2 %0, %1, %2, %3;" : "=l"(d) : "l"(a), "l"(b), "l"(c)); return d;
}
__device__ __forceinline__ float2 upk(ull v) {
    float2 r; asm("mov.b64 {%0, %1}, %2;" : "=f"(r.x), "=f"(r.y) : "l"(v)); return r;
}

// ---------------- scratch (device globals: no allocation allowed) ----------
__device__ float g_Q[ROWS*DM];
__device__ float g_K[ROWS*DM];
__device__ float g_V[ROWS*DM];
__device__ float g_ctx[ROWS*DM];

// ---------------- SGEMM: C = (A @ W + bias) * scale ------------------------
// A: [8192,1024] row-major, W: [1024,1024] row-major.
// head_mode=1: write [B,H,S,DH] layout; head_mode=0: plain row-major.
// BM=128, BN=64, BK=16, 256 threads, thread tile 8x4 (4 row-pairs x 4 cols).
__global__ void __launch_bounds__(256) gemm128x64(
    const float* __restrict__ A, const float* __restrict__ W,
    const float* __restrict__ bias, float* __restrict__ out,
    float scale, int head_mode)
{
    __shared__ float As[16][132];       // transposed A tile, padded
    __shared__ ull   Bs2[16][64];       // W tile, each value duplicated in a pair

    const int Kd = DM, Nd = DM;
    int tid   = threadIdx.x;
    int rbase = blockIdx.y * 128;
    int nbase = blockIdx.x * 64;
    int tm = tid >> 4;   // 0..15 -> row group of 8
    int tn = tid & 15;   // 0..15 -> col group of 4

    ull acc[4][4];
    #pragma unroll
    for (int i = 0; i < 4; i++)
        #pragma unroll
        for (int j = 0; j < 4; j++) acc[i][j] = 0ULL;

    for (int kt = 0; kt < Kd; kt += 16) {
        // A tile: 128 rows x 16 cols = 512 float4
        #pragma unroll
        for (int q = 0; q < 2; q++) {
            int id = tid * 2 + q;
            int r  = id >> 2, c4 = id & 3;
            float4 v = *(const float4*)&A[(size_t)(rbase + r) * Kd + kt + c4 * 4];
            As[c4*4+0][r] = v.x; As[c4*4+1][r] = v.y;
            As[c4*4+2][r] = v.z; As[c4*4+3][r] = v.w;
        }
        // W tile: 16 x 64, duplicated pairs
        {
            int kr = tid >> 4, c4 = tid & 15;
            float4 v = *(const float4*)&W[(size_t)(kt + kr) * Nd + nbase + c4 * 4];
            Bs2[kr][c4*4+0] = pk(v.x, v.x);
            Bs2[kr][c4*4+1] = pk(v.y, v.y);
            Bs2[kr][c4*4+2] = pk(v.z, v.z);
            Bs2[kr][c4*4+3] = pk(v.w, v.w);
        }
        __syncthreads();
        #pragma unroll
        for (int k = 0; k < 16; k++) {
            ulonglong2 a0 = *(const ulonglong2*)&As[k][tm * 8];
            ulonglong2 a1 = *(const ulonglong2*)&As[k][tm * 8 + 4];
            ulonglong2 b0 = *(const ulonglong2*)&Bs2[k][tn * 4];
            ulonglong2 b1 = *(const ulonglong2*)&Bs2[k][tn * 4 + 2];
            ull am[4] = {a0.x, a0.y, a1.x, a1.y};
            ull bn[4] = {b0.x, b0.y, b1.x, b1.y};
            #pragma unroll
            for (int mp = 0; mp < 4; mp++)
                #pragma unroll
                for (int n = 0; n < 4; n++)
                    acc[mp][n] = fma2_(am[mp], bn[n], acc[mp][n]);
        }
        __syncthreads();
    }

    float bb[4];
    #pragma unroll
    for (int n = 0; n < 4; n++) bb[n] = bias[nbase + tn * 4 + n];

    #pragma unroll
    for (int mp = 0; mp < 4; mp++) {
        int r0 = rbase + tm * 8 + mp * 2;
        #pragma unroll
        for (int n = 0; n < 4; n++) {
            float2 p = upk(acc[mp][n]);
            int col = nbase + tn * 4 + n;
            float v0 = (p.x + bb[n]) * scale;
            float v1 = (p.y + bb[n]) * scale;
            if (head_mode) {
                int bi = r0 >> 11;          // / 2048
                int s0 = r0 & 2047;
                int hh = col >> 6, dd = col & 63;
                size_t base = ((size_t)(bi * HH + hh) * SS + s0) * DH + dd;
                out[base]      = v0;
                out[base + DH] = v1;        // s0+1 (tiles never cross batch)
            } else {
                out[(size_t)r0 * Nd + col]       = v0;
                out[(size_t)(r0 + 1) * Nd + col] = v1;
            }
        }
    }
}

// ---------------- attention: scores + softmax + attn write + attn@V --------
// grid (S/16, H, B), 256 threads. smem: sc[16][2048] + qs[16][64] + 2x kv[128][68]
#define QT 16
#define JT 128
#define NJT (SS/JT)
#define KVPAD 68
#define ATTN_SMEM ((QT*SS + QT*DH + 2*JT*KVPAD) * 4)   // 204800 bytes

__global__ void __launch_bounds__(256) attn_kernel(
    const float* __restrict__ Qp, const float* __restrict__ Kp,
    const float* __restrict__ Vp, float* __restrict__ attn_out,
    float* __restrict__ ctx, int write_attn)
{
    extern __shared__ float smem[];
    float* sc  = smem;                    // 16*2048
    float* qs  = smem + QT * SS;          // 16*64
    float* kv0 = qs + QT * DH;            // 128*68
    float* kv1 = kv0 + JT * KVPAD;

    int tid = threadIdx.x;
    int b = blockIdx.z, h = blockIdx.y, qt = blockIdx.x;
    size_t bh = (size_t)b * HH + h;
    const float* Qb = Qp + (bh * SS + (size_t)qt * QT) * DH;
    const float* Kb = Kp + bh * SS * DH;
    const float* Vb = Vp + bh * SS * DH;

    // Q tile: 1024 floats flat
    *(float4*)&qs[tid * 4] = *(const float4*)&Qb[tid * 4];
    // K tile 0 -> kv0 (32KB, coalesced, padded rows)
    {
        const float4* g = (const float4*)Kb;
        #pragma unroll
        for (int r = 0; r < 8; r++) {
            int idx = tid + r * 256;
            int row = idx >> 4, c4 = idx & 15;
            *(float4*)&kv0[row * KVPAD + c4 * 4] = g[idx];
        }
    }
    __syncthreads();

    int wi = tid >> 5;   // warp 0..7
    int tj = tid & 31;

    // ---- scores: 16 x 2048 in j-tiles of 128, K double-buffered ----
    for (int jt = 0; jt < NJT; jt++) {
        float* cur = (jt & 1) ? kv1 : kv0;
        float* nxt = (jt & 1) ? kv0 : kv1;
        bool pre = (jt + 1 < NJT);
        float4 stage[8];
        if (pre) {
            const float4* g = (const float4*)(Kb + (size_t)(jt + 1) * JT * DH);
            #pragma unroll
            for (int r = 0; r < 8; r++) stage[r] = g[tid + r * 256];
        }
        ull acc2[2][4];
        #pragma unroll
        for (int ii = 0; ii < 2; ii++)
            #pragma unroll
            for (int jj = 0; jj < 4; jj++) acc2[ii][jj] = 0ULL;

        #pragma unroll
        for (int d4 = 0; d4 < 16; d4++) {
            ulonglong2 q0 = *(const ulonglong2*)&qs[wi * DH + d4 * 4];
            ulonglong2 q1 = *(const ulonglong2*)&qs[(wi + 8) * DH + d4 * 4];
            #pragma unroll
            for (int jj = 0; jj < 4; jj++) {
                ulonglong2 kk = *(const ulonglong2*)&cur[(tj + jj * 32) * KVPAD + d4 * 4];
                acc2[0][jj] = fma2_(q0.x, kk.x, acc2[0][jj]);
                acc2[0][jj] = fma2_(q0.y, kk.y, acc2[0][jj]);
                acc2[1][jj] = fma2_(q1.x, kk.x, acc2[1][jj]);
                acc2[1][jj] = fma2_(q1.y, kk.y, acc2[1][jj]);
            }
        }
        #pragma unroll
        for (int ii = 0; ii < 2; ii++)
            #pragma unroll
            for (int jj = 0; jj < 4; jj++) {
                float2 p = upk(acc2[ii][jj]);
                sc[(size_t)(wi + ii * 8) * SS + jt * JT + tj + jj * 32] = p.x + p.y;
            }
        if (pre) {
            #pragma unroll
            for (int r = 0; r < 8; r++) {
                int idx = tid + r * 256;
                int row = idx >> 4, c4 = idx & 15;
                *(float4*)&nxt[row * KVPAD + c4 * 4] = stage[r];
            }
        }
        __syncthreads();
    }

    // ---- V tile 0 preload (kv0 is free: last K tile lives in kv1) ----
    {
        const float4* g = (const float4*)Vb;
        #pragma unroll
        for (int r = 0; r < 8; r++) {
            int idx = tid + r * 256;
            int row = idx >> 4, c4 = idx & 15;
            *(float4*)&kv0[row * KVPAD + c4 * 4] = g[idx];
        }
    }

    // ---- softmax: warp wi handles rows wi and wi+8 (warp-local) ----
    #pragma unroll
    for (int ii = 0; ii < 2; ii++) {
        float4* row4 = (float4*)(sc + (size_t)(wi + ii * 8) * SS);
        float m = -3.4e38f;
        for (int j = tj; j < SS / 4; j += 32) {
            float4 t = row4[j];
            m = fmaxf(m, fmaxf(fmaxf(t.x, t.y), fmaxf(t.z, t.w)));
        }
        #pragma unroll
        for (int o = 16; o; o >>= 1) m = fmaxf(m, __shfl_xor_sync(0xffffffffu, m, o));
        float sum = 0.f;
        for (int j = tj; j < SS / 4; j += 32) {
            float4 t = row4[j];
            t.x = __expf(t.x - m); t.y = __expf(t.y - m);
            t.z = __expf(t.z - m); t.w = __expf(t.w - m);
            row4[j] = t;
            sum += t.x + t.y + t.z + t.w;
        }
        #pragma unroll
        for (int o = 16; o; o >>= 1) sum += __shfl_xor_sync(0xffffffffu, sum, o);
        float inv = 1.f / sum;
        for (int j = tj; j < SS / 4; j += 32) {
            float4 t = row4[j];
            t.x *= inv; t.y *= inv; t.z *= inv; t.w *= inv;
            row4[j] = t;
        }
    }
    __syncthreads();

    // ---- write attention probabilities (16 rows contiguous) ----
    if (write_attn) {
        float4* dst = (float4*)(attn_out + (bh * SS + (size_t)qt * QT) * SS);
        const float4* src = (const float4*)sc;
        #pragma unroll
        for (int r = 0; r < 32; r++) dst[tid + r * 256] = src[tid + r * 256];
    }

    // ---- attn @ V : thread owns (row i, 4 consecutive d) ----
    int i  = tid >> 4;      // 0..15
    int dq = tid & 15;      // d quad
    ull o0 = 0ULL, o1 = 0ULL;
    for (int jt = 0; jt < NJT; jt++) {
        float* cur = (jt & 1) ? kv1 : kv0;
        float* nxt = (jt & 1) ? kv0 : kv1;
        bool pre = (jt + 1 < NJT);
        float4 stage[8];
        if (pre) {
            const float4* g = (const float4*)(Vb + (size_t)(jt + 1) * JT * DH);
            #pragma unroll
            for (int r = 0; r < 8; r++) stage[r] = g[tid + r * 256];
        }
        const float* prow = sc + (size_t)i * SS + jt * JT;
        #pragma unroll 4
        for (int j = 0; j < JT; j++) {
            float p = prow[j];
            ull pp = pk(p, p);
            ulonglong2 v = *(const ulonglong2*)&cur[j * KVPAD + dq * 4];
            o0 = fma2_(pp, v.x, o0);
            o1 = fma2_(pp, v.y, o1);
        }
        if (pre) {
            #pragma unroll
            for (int r = 0; r < 8; r++) {
                int idx = tid + r * 256;
                int row = idx >> 4, c4 = idx & 15;
                *(float4*)&nxt[row * KVPAD + c4 * 4] = stage[r];
            }
        }
        __syncthreads();
    }
    float2 lo = upk(o0), hi = upk(o1);
    float4 res = make_float4(lo.x, lo.y, hi.x, hi.y);
    *(float4*)&ctx[((size_t)b * SS + (size_t)qt * QT + i) * DM + h * DH + dq * 4] = res;
}

// ---------------------------------------------------------------------------
extern "C" void kernel_launch(void* const* d_in, const int* in_sizes, int n_in,
                              void* d_out, int out_size)
{
    const float* q  = (const float*)d_in[0];
    const float* k  = (const float*)d_in[1];
    const float* v  = (const float*)d_in[2];
    const float* Wq = (const float*)d_in[3];
    const float* bq = (const float*)d_in[4];
    const float* Wk = (const float*)d_in[5];
    const float* bk = (const float*)d_in[6];
    const float* Wv = (const float*)d_in[7];
    const float* bv = (const float*)d_in[8];
    const float* Wo = (const float*)d_in[9];
    const float* bo = (const float*)d_in[10];

    float* outp = (float*)d_out;
    float* final_dst = nullptr;
    float* attn_dst  = nullptr;
    int write_attn = 0;
    long long osz = (long long)out_size;
    if (osz >= OUTE + ATTNE) {            // (out, attn) concatenated
        final_dst = outp;
        attn_dst  = outp + OUTE;
        write_attn = 1;
    } else if (osz == ATTNE) {            // attn only
        attn_dst = outp;
        write_attn = 1;
    } else {                              // out only
        final_dst = outp;
    }

    float *pQ, *pK, *pV, *pC;
    cudaGetSymbolAddress((void**)&pQ, g_Q);
    cudaGetSymbolAddress((void**)&pK, g_K);
    cudaGetSymbolAddress((void**)&pV, g_V);
    cudaGetSymbolAddress((void**)&pC, g_ctx);

    cudaFuncSetAttribute(attn_kernel, cudaFuncAttributeMaxDynamicSharedMemorySize,
                         ATTN_SMEM);

    dim3 gb(DM / 64, ROWS / 128);
    const float qscale = 0.125f;  // 1/sqrt(DH)
    gemm128x64<<<gb, 256>>>(q, Wq, bq, pQ, qscale, 1);
    gemm128x64<<<gb, 256>>>(k, Wk, bk, pK, 1.0f,   1);
    gemm128x64<<<gb, 256>>>(v, Wv, bv, pV, 1.0f,   1);

    dim3 ga(SS / QT, HH, BB);
    attn_kernel<<<ga, 256, ATTN_SMEM>>>(pQ, pK, pV, attn_dst, pC, write_attn);

    if (final_dst)
        gemm128x64<<<gb, 256>>>(pC, Wo, bo, final_dst, 1.0f, 0);
}